// round 14
// baseline (speedup 1.0000x reference)
#include <cuda_runtime.h>
#include <cuda_fp16.h>
#include <math.h>

#define BB 4
#define SS 2048
#define DD 1024
#define HH 16
#define MROWS (BB*SS)   // 8192

// Scratch (device globals). f16 tensors use the "sigma" pair permutation
// within each 64-element k-block (pairs p=8ks+4h+q -> slot q*8+2ks+h).
__device__ __half   g_Qh[BB*SS*DD];   // Q*0.125*log2e, f16 sigma
__device__ __half   g_Kh[BB*SS*DD];   // K, f16 sigma
__device__ __half   g_Vh[BB*SS*DD];   // f16 V^T: [b*H+h][64 d][2048 kv, sigma per 64-tile]
__device__ __half   g_Ch[BB*SS*DD];   // ctx, f16 sigma
__device__ __half   g_Xq[MROWS*DD];
__device__ __half   g_Xk[MROWS*DD];
__device__ __half   g_Xv[MROWS*DD];
__device__ __half   g_Wqh[DD*DD];
__device__ __half   g_Wkh[DD*DD];
__device__ __half   g_Wvh[DD*DD];
__device__ __half   g_Woh[DD*DD];

// ---------------------------------------------------------------------------
// helpers
// ---------------------------------------------------------------------------
__device__ __forceinline__ unsigned packh2(float lo, float hi) {
    __half2 h = __floats2half2_rn(lo, hi);
    return *(unsigned*)&h;
}
__device__ __forceinline__ unsigned ex2h2(unsigned x) {
    unsigned r;
    asm("ex2.approx.f16x2 %0, %1;" : "=r"(r) : "r"(x));
    return r;
}
__device__ __forceinline__ void mma_f16(float* d, const unsigned* a,
                                        const unsigned* b, const float* c) {
    asm volatile(
        "mma.sync.aligned.m16n8k16.row.col.f32.f16.f16.f32 "
        "{%0,%1,%2,%3}, {%4,%5,%6,%7}, {%8,%9}, {%10,%11,%12,%13};\n"
        : "=f"(d[0]), "=f"(d[1]), "=f"(d[2]), "=f"(d[3])
        : "r"(a[0]), "r"(a[1]), "r"(a[2]), "r"(a[3]),
          "r"(b[0]), "r"(b[1]),
          "f"(c[0]), "f"(c[1]), "f"(c[2]), "f"(c[3]));
}
__device__ __forceinline__ void cp16(void* smem, const void* g) {
    unsigned s = (unsigned)__cvta_generic_to_shared(smem);
    asm volatile("cp.async.cg.shared.global [%0], [%1], 16;\n" :: "r"(s), "l"(g));
}
#define CP_COMMIT asm volatile("cp.async.commit_group;\n")
#define CP_WAIT2  asm volatile("cp.async.wait_group 2;\n")
#define CP_WAIT1  asm volatile("cp.async.wait_group 1;\n")
#define CP_WAIT0  asm volatile("cp.async.wait_group 0;\n")

// sigma: pair p = 8ks + 4h + q  ->  slot q*8 + 2ks + h  (u32-pair domain)
__device__ __forceinline__ int sigma(int p) {
    return (p & 3) * 8 + ((p >> 3) << 1) + ((p >> 2) & 1);
}

// ---------------------------------------------------------------------------
// Prep: fp32 -> f16 pairs, sigma-permuted per 64-element block
// ---------------------------------------------------------------------------
__device__ __forceinline__ void cvt_sigma(const float* __restrict__ src,
                                          unsigned* __restrict__ dst) {
    size_t i = ((size_t)blockIdx.x * 256 + threadIdx.x) * 4;
    float4 v = *(const float4*)(src + i);
    size_t base = (i >> 1) & ~(size_t)31;
    int p0 = (int)(i & 63) >> 1;
    dst[base + sigma(p0)    ] = packh2(v.x, v.y);
    dst[base + sigma(p0 + 1)] = packh2(v.z, v.w);
}
__global__ __launch_bounds__(256) void cvt_in(
    const float* __restrict__ a, const float* __restrict__ b,
    const float* __restrict__ c,
    unsigned* __restrict__ oa, unsigned* __restrict__ ob, unsigned* __restrict__ oc)
{
    const float* src = (blockIdx.z == 0) ? a : (blockIdx.z == 1) ? b : c;
    unsigned*    dst = (blockIdx.z == 0) ? oa : (blockIdx.z == 1) ? ob : oc;
    cvt_sigma(src, dst);
}
__global__ __launch_bounds__(256) void cvt_w(
    const float* __restrict__ a, const float* __restrict__ b,
    const float* __restrict__ c, const float* __restrict__ d,
    unsigned* __restrict__ oa, unsigned* __restrict__ ob,
    unsigned* __restrict__ oc, unsigned* __restrict__ od)
{
    const float* src = (blockIdx.z == 0) ? a : (blockIdx.z == 1) ? b
                     : (blockIdx.z == 2) ? c : d;
    unsigned*    dst = (blockIdx.z == 0) ? oa : (blockIdx.z == 1) ? ob
                     : (blockIdx.z == 2) ? oc : od;
    cvt_sigma(src, dst);
}

// ---------------------------------------------------------------------------
// fp16 GEMM v2: warp tile 64x64, CTA tile 128x256, 8 warps (2x4), 3-stage
// cp.async pipeline. A fragments cached across all 8 n-tiles -> crossbar
// bytes per mma halve vs v1 (A redundancy 4x->2x). 1 CTA/SM (~230 regs).
// Per-output k-order identical to v1 -> bitwise-identical results.
// ---------------------------------------------------------------------------
#define GSTR 36
#define ASTG (128 * GSTR)            // u32 per A stage
#define BSTG (256 * GSTR)            // u32 per B stage
#define GSTG (ASTG + BSTG)           // u32 per stage (55296 B)
template<int PERM>
__device__ __forceinline__ void gemm_body(
    const unsigned* __restrict__ A, const unsigned* __restrict__ W,
    const float* __restrict__ bias, void* __restrict__ Cv,
    int M, int N, int K, float oscale)
{
    extern __shared__ unsigned smu[];

    const int tid  = threadIdx.x;
    const int lane = tid & 31, warp = tid >> 5;
    const int wy = warp >> 2, wx = warp & 3;
    const int m0 = wy * 64, n0 = wx * 64;
    const int r = lane >> 2, q = lane & 3;
    const int bm = blockIdx.y * 128, bn = blockIdx.x * 256;
    const int K2 = K >> 1;

    float acc[4][8][4];
    #pragma unroll
    for (int mt = 0; mt < 4; mt++)
        #pragma unroll
        for (int nt = 0; nt < 8; nt++)
            #pragma unroll
            for (int i = 0; i < 4; i++) acc[mt][nt][i] = 0.0f;

    const int NK = K / 64;   // 16

    auto load_stage = [&](int kt, int buf) {
        const unsigned* Ag = A + (size_t)bm * K2 + kt * 32;
        const unsigned* Wg = W + (size_t)bn * K2 + kt * 32;
        unsigned* as = smu + buf * GSTG;
        unsigned* ws = as + ASTG;
        #pragma unroll
        for (int i = 0; i < 4; i++) {               // A: 1024 chunks
            int idx = tid + i * 256;
            int row = idx >> 3, u = idx & 7;
            cp16(&as[row * GSTR + u * 4], Ag + (size_t)row * K2 + u * 4);
        }
        #pragma unroll
        for (int i = 0; i < 8; i++) {               // B: 2048 chunks
            int idx = tid + i * 256;
            int row = idx >> 3, u = idx & 7;
            cp16(&ws[row * GSTR + u * 4], Wg + (size_t)row * K2 + u * 4);
        }
        CP_COMMIT;
    };

    load_stage(0, 0);
    if (NK > 1) load_stage(1, 1);

    for (int kt = 0; kt < NK; kt++) {
        if (kt + 1 < NK) { CP_WAIT1; } else { CP_WAIT0; }
        __syncthreads();
        if (kt + 2 < NK) load_stage(kt + 2, (kt + 2) % 3);

        const unsigned* as = smu + (kt % 3) * GSTG;
        const unsigned* ws = as + ASTG;

        // cache A fragments for all 4 m-tiles (64 regs, reused by 8 n-tiles)
        unsigned af[4][4][4];
        #pragma unroll
        for (int mt = 0; mt < 4; mt++) {
            const uint4* ap0 = (const uint4*)(as + (m0 + mt * 16 + r    ) * GSTR + q * 8);
            const uint4* ap1 = (const uint4*)(as + (m0 + mt * 16 + r + 8) * GSTR + q * 8);
            uint4 a00 = ap0[0], a01 = ap0[1], a10 = ap1[0], a11 = ap1[1];
            unsigned ar0[8] = {a00.x,a00.y,a00.z,a00.w, a01.x,a01.y,a01.z,a01.w};
            unsigned ar1[8] = {a10.x,a10.y,a10.z,a10.w, a11.x,a11.y,a11.z,a11.w};
            #pragma unroll
            for (int ks = 0; ks < 4; ks++) {
                af[mt][ks][0] = ar0[2*ks];
                af[mt][ks][1] = ar1[2*ks];
                af[mt][ks][2] = ar0[2*ks+1];
                af[mt][ks][3] = ar1[2*ks+1];
            }
        }

        #pragma unroll
        for (int nt = 0; nt < 8; nt++) {
            const uint4* bp = (const uint4*)(ws + (n0 + nt * 8 + r) * GSTR + q * 8);
            uint4 u0 = bp[0], u1 = bp[1];
            unsigned bch[8] = {u0.x,u0.y,u0.z,u0.w, u1.x,u1.y,u1.z,u1.w};
            #pragma unroll
            for (int mt = 0; mt < 4; mt++) {
                #pragma unroll
                for (int ks = 0; ks < 4; ks++) {
                    unsigned bf[2] = { bch[2*ks], bch[2*ks+1] };
                    mma_f16(acc[mt][nt], af[mt][ks], bf, acc[mt][nt]);
                }
            }
        }
    }

    if (PERM == 3) {
        __syncthreads();
        // V^T through smem: [256 d][136 tokens] f16, then coalesced sigma write
        __half* Vts = (__half*)smu;
        #pragma unroll
        for (int mt = 0; mt < 4; mt++) {
            #pragma unroll
            for (int nt = 0; nt < 8; nt++) {
                int col = bn + n0 + nt * 8 + 2 * q;
                float2 bv = *(const float2*)&bias[col];
                int tok = m0 + mt * 16 + r;
                int dc  = n0 + nt * 8 + 2 * q;      // local d col 0..255
                Vts[ dc      * 136 + tok    ] = __float2half_rn(acc[mt][nt][0] + bv.x);
                Vts[(dc + 1) * 136 + tok    ] = __float2half_rn(acc[mt][nt][1] + bv.y);
                Vts[ dc      * 136 + tok + 8] = __float2half_rn(acc[mt][nt][2] + bv.x);
                Vts[(dc + 1) * 136 + tok + 8] = __float2half_rn(acc[mt][nt][3] + bv.y);
            }
        }
        __syncthreads();
        const unsigned* Vtu = (const unsigned*)Vts;   // stride 68 u32
        unsigned* Co = (unsigned*)Cv;
        #pragma unroll 4
        for (int i = 0; i < 64; i++) {
            int f = tid + i * 256;                // 256 d x 64 u32 slots
            int d = f >> 6, slot = f & 63;
            int tile = slot >> 5, g = slot & 31;
            int p = ((g >> 1) & 3) * 8 + (g & 1) * 4 + (g >> 3);  // sigma^-1
            unsigned val = Vtu[d * 68 + tile * 32 + p];
            int gc = bn + d;
            int head = gc >> 6, dl = gc & 63;
            int bb = (bm + tile * 64) >> 11;
            int tib = ((bm & 2047) >> 6) + tile;
            Co[((size_t)(bb * HH + head) * 64 + dl) * 1024 + (size_t)tib * 32 + g] = val;
        }
        return;
    }

    #pragma unroll
    for (int mt = 0; mt < 4; mt++) {
        #pragma unroll
        for (int nt = 0; nt < 8; nt++) {
            int col = bn + n0 + nt * 8 + 2 * q;
            float2 bv = *(const float2*)&bias[col];
            int row0 = bm + m0 + mt * 16 + r;
            float v00 = (acc[mt][nt][0] + bv.x) * oscale;
            float v01 = (acc[mt][nt][1] + bv.y) * oscale;
            float v10 = (acc[mt][nt][2] + bv.x) * oscale;
            float v11 = (acc[mt][nt][3] + bv.y) * oscale;
            if (PERM == 0) {
                float* Cf = (float*)Cv;
                *(float2*)&Cf[(size_t)row0     * N + col] = make_float2(v00, v01);
                *(float2*)&Cf[(size_t)(row0+8) * N + col] = make_float2(v10, v11);
            } else {  // PERM 1: f16 sigma
                unsigned* Cu = (unsigned*)Cv;
                int slot = sigma((col & 63) >> 1);
                size_t base = (size_t)row0 * (N >> 1) + ((col >> 6) << 5) + slot;
                Cu[base]                 = packh2(v00, v01);
                Cu[base + 8 * (N >> 1)]  = packh2(v10, v11);
            }
        }
    }
}

__global__ __launch_bounds__(256, 1) void gemm_qkv(
    const unsigned* __restrict__ xq, const unsigned* __restrict__ xk, const unsigned* __restrict__ xv,
    const unsigned* __restrict__ Wq, const unsigned* __restrict__ Wk, const unsigned* __restrict__ Wv,
    const float* __restrict__ bq, const float* __restrict__ bk, const float* __restrict__ bv,
    __half* __restrict__ Qd, __half* __restrict__ Kd, __half* __restrict__ Vd)
{
    const int z = blockIdx.z;
    if      (z == 0) gemm_body<1>(xq, Wq, bq, (void*)Qd, MROWS, DD, DD, 0.18033688f);
    else if (z == 1) gemm_body<1>(xk, Wk, bk, (void*)Kd, MROWS, DD, DD, 1.0f);
    else             gemm_body<3>(xv, Wv, bv, (void*)Vd, MROWS, DD, DD, 1.0f);
}

__global__ __launch_bounds__(256, 1) void gemm_out(
    const unsigned* __restrict__ A, const unsigned* __restrict__ W,
    const float* __restrict__ bias, float* __restrict__ C)
{
    gemm_body<0>(A, W, bias, (void*)C, MROWS, DD, DD, 1.0f);
}

// ---------------------------------------------------------------------------
// fp16 flash attention v13 (unchanged, 173us): 32 q-rows/warp, 128-thr CTAs,
// 3 CTAs/SM, two key-pair passes per tile so pa liveness stays at 16 regs.
// ---------------------------------------------------------------------------
#define KVSTR 36
#define QT   128
#define KVSTG (2 * 64 * KVSTR)
__global__ __launch_bounds__(128, 3) void attn_tc(
    const unsigned* __restrict__ Q, const unsigned* __restrict__ K,
    const unsigned* __restrict__ V, unsigned* __restrict__ Out)
{
    extern __shared__ unsigned smu[];
    unsigned* Qs = smu + 3 * KVSTG;   // [128][36] u32

    const int tid  = threadIdx.x;
    const int lane = tid & 31, warp = tid >> 5;   // 4 warps
    const int m0 = warp * 32;                     // 32 q-rows per warp
    const int r = lane >> 2, q = lane & 3;
    const int qt = blockIdx.x, bh = blockIdx.y;
    const int b = bh >> 4, h = bh & 15;

    const unsigned* Qg = Q + ((size_t)(b * SS + qt * QT)) * 512 + h * 32;
    const unsigned* Kg = K + ((size_t)(b * SS)) * 512 + h * 32;
    const unsigned* Vg = V + ((size_t)(b * HH + h) * 64) * 1024;

    #pragma unroll
    for (int i = 0; i < 8; i++) {
        int idx = tid + i * 128;
        int row = idx >> 3, u = idx & 7;
        cp16(&Qs[row * KVSTR + u * 4], Qg + (size_t)row * 512 + u * 4);
    }
    CP_COMMIT;

    auto load_stage = [&](int kt, int buf) {
        unsigned* ks_ = smu + buf * KVSTG;
        unsigned* vs_ = ks_ + 64 * KVSTR;
        #pragma unroll
        for (int i = 0; i < 4; i++) {
            int idx = tid + i * 128;
            int row = idx >> 3, u = idx & 7;
            cp16(&ks_[row * KVSTR + u * 4], Kg + (size_t)(kt * 64 + row) * 512 + u * 4);
            cp16(&vs_[row * KVSTR + u * 4], Vg + (size_t)row * 1024 + kt * 32 + u * 4);
        }
        CP_COMMIT;
    };
    load_stage(0, 0);
    load_stage(1, 1);

    CP_WAIT2;          // Q done
    __syncthreads();

    unsigned qa[2][4][4];
    #pragma unroll
    for (int mt = 0; mt < 2; mt++) {
        const uint4* qp0 = (const uint4*)(Qs + (m0 + mt * 16 + r    ) * KVSTR + q * 8);
        const uint4* qp1 = (const uint4*)(Qs + (m0 + mt * 16 + r + 8) * KVSTR + q * 8);
        uint4 a00 = qp0[0], a01 = qp0[1], a10 = qp1[0], a11 = qp1[1];
        unsigned ar0[8] = {a00.x,a00.y,a00.z,a00.w, a01.x,a01.y,a01.z,a01.w};
        unsigned ar1[8] = {a10.x,a10.y,a10.z,a10.w, a11.x,a11.y,a11.z,a11.w};
        #pragma unroll
        for (int ks = 0; ks < 4; ks++) {
            qa[mt][ks][0] = ar0[2*ks];
            qa[mt][ks][1] = ar1[2*ks];
            qa[mt][ks][2] = ar0[2*ks+1];
            qa[mt][ks][3] = ar1[2*ks+1];
        }
    }

    float O[2][8][4];
    #pragma unroll
    for (int mt = 0; mt < 2; mt++)
        #pragma unroll
        for (int nt = 0; nt < 8; nt++)
            #pragma unroll
            for (int i = 0; i < 4; i++) O[mt][nt][i] = 0.0f;
    float Ol[2][4] = {};
    const unsigned onesb[2] = { 0x3C003C00u, 0x3C003C00u };

    const int NT = SS / 64;
    for (int kt = 0; kt < NT; kt++) {
        if (kt + 1 < NT) { CP_WAIT1; } else { CP_WAIT0; }
        __syncthreads();
        if (kt + 2 < NT) load_stage(kt + 2, (kt + 2) % 3);

        const unsigned* Ks = smu + (kt % 3) * KVSTG;
        const unsigned* Vs = Ks + 64 * KVSTR;

        #pragma unroll
        for (int tp = 0; tp < 2; tp++) {
            unsigned pa[2][2][4];
            #pragma unroll
            for (int ntl = 0; ntl < 4; ntl++) {
                int nt = tp * 4 + ntl;
                const uint4* kp = (const uint4*)(Ks + (nt * 8 + r) * KVSTR + q * 8);
                uint4 u0 = kp[0], u1 = kp[1];
                unsigned ch[8] = {u0.x,u0.y,u0.z,u0.w, u1.x,u1.y,u1.z,u1.w};
                float sf0[4] = {0,0,0,0}, sf1[4] = {0,0,0,0};
                #pragma unroll
                for (int ks = 0; ks < 4; ks++) {
                    unsigned bf[2] = { ch[2*ks], ch[2*ks+1] };
                    mma_f16(sf0, qa[0][ks], bf, sf0);
                    mma_f16(sf1, qa[1][ks], bf, sf1);
                }
                int tl = ntl >> 1, j = ntl & 1;
                pa[0][tl][2*j    ] = ex2h2(packh2(sf0[0], sf0[1]));
                pa[0][tl][2*j + 1] = ex2h2(packh2(sf0[2], sf0[3]));
                pa[1][tl][2*j    ] = ex2h2(packh2(sf1[0], sf1[1]));
                pa[1][tl][2*j + 1] = ex2h2(packh2(sf1[2], sf1[3]));
            }

            #pragma unroll
            for (int tl = 0; tl < 2; tl++) {
                mma_f16(Ol[0], pa[0][tl], onesb, Ol[0]);
                mma_f16(Ol[1], pa[1][tl], onesb, Ol[1]);
            }

            #pragma unroll
            for (int nt = 0; nt < 8; nt++) {
                uint4 v = *(const uint4*)(Vs + (nt * 8 + r) * KVSTR + q * 8 + tp * 4);
                unsigned bf0[2] = { v.x, v.y };
                unsigned bf1[2] = { v.z, v.w };
                mma_f16(O[0][nt], pa[0][0], bf0, O[0][nt]);
                mma_f16(O[0][nt], pa[0][1], bf1, O[0][nt]);
                mma_f16(O[1][nt], pa[1][0], bf0, O[1][nt]);
                mma_f16(O[1][nt], pa[1][1], bf1, O[1][nt]);
            }
        }
    }

    unsigned* Og = Out + ((size_t)(b * SS + qt * QT)) * 512 + h * 32;
    #pragma unroll
    for (int mt = 0; mt < 2; mt++) {
        float inv0 = 1.0f / Ol[mt][0], inv1 = 1.0f / Ol[mt][2];
        #pragma unroll
        for (int nt = 0; nt < 8; nt++) {
            int c0 = nt * 8 + 2 * q;
            int slot = sigma(c0 >> 1);
            size_t ra = (size_t)(m0 + mt * 16 + r    ) * 512;
            size_t rb = (size_t)(m0 + mt * 16 + r + 8) * 512;
            Og[ra + slot] = packh2(O[mt][nt][0] * inv0, O[mt][nt][1] * inv0);
            Og[rb + slot] = packh2(O[mt][nt][2] * inv1, O[mt][nt][3] * inv1);
        }
    }
}

// ---------------------------------------------------------------------------
extern "C" void kernel_launch(void* const* d_in, const int* in_sizes, int n_in,
                              void* d_out, int out_size)
{
    const float* query = (const float*)d_in[0];
    const float* key_  = (const float*)d_in[1];
    const float* value = (const float*)d_in[2];
    const float* Wq    = (const float*)d_in[3];
    const float* bq    = (const float*)d_in[4];
    const float* Wk    = (const float*)d_in[5];
    const float* bk    = (const float*)d_in[6];
    const float* Wv    = (const float*)d_in[7];
    const float* bv    = (const float*)d_in[8];
    const float* Wo    = (const float*)d_in[9];
    const float* bo    = (const float*)d_in[10];
    float* out = (float*)d_out;

    __half *Qd, *Kd, *Vd, *Cd, *Xq, *Xk, *Xv, *Wqh, *Wkh, *Wvh, *Woh;
    cudaGetSymbolAddress((void**)&Qd,  g_Qh);
    cudaGetSymbolAddress((void**)&Kd,  g_Kh);
    cudaGetSymbolAddress((void**)&Vd,  g_Vh);
    cudaGetSymbolAddress((void**)&Cd,  g_Ch);
    cudaGetSymbolAddress((void**)&Xq,  g_Xq);
    cudaGetSymbolAddress((void**)&Xk,  g_Xk);
    cudaGetSymbolAddress((void**)&Xv,  g_Xv);
    cudaGetSymbolAddress((void**)&Wqh, g_Wqh);
    cudaGetSymbolAddress((void**)&Wkh, g_Wkh);
    cudaGetSymbolAddress((void**)&Wvh, g_Wvh);
    cudaGetSymbolAddress((void**)&Woh, g_Woh);

    const int gemm_smem = 3 * GSTG * 4;                         // 165888
    const int attn_smem = (3 * KVSTG + QT * KVSTR) * 4;         // 73728
    cudaFuncSetAttribute(gemm_qkv, cudaFuncAttributeMaxDynamicSharedMemorySize, gemm_smem);
    cudaFuncSetAttribute(gemm_out, cudaFuncAttributeMaxDynamicSharedMemorySize, gemm_smem);
    cudaFuncSetAttribute(attn_tc,  cudaFuncAttributeMaxDynamicSharedMemorySize, attn_smem);

    cvt_in<<<dim3(MROWS*DD/4/256, 1, 3), 256>>>(query, key_, value,
                                                (unsigned*)Xq, (unsigned*)Xk, (unsigned*)Xv);
    cvt_w <<<dim3(DD*DD/4/256,   1, 4), 256>>>(Wq, Wk, Wv, Wo,
                                               (unsigned*)Wqh, (unsigned*)Wkh,
                                               (unsigned*)Wvh, (unsigned*)Woh);

    dim3 qkvgrid(DD / 256, MROWS / 128, 3);   // (4, 64, 3)
    gemm_qkv<<<qkvgrid, 256, gemm_smem>>>((const unsigned*)Xq, (const unsigned*)Xk,
                                          (const unsigned*)Xv, (const unsigned*)Wqh,
                                          (const unsigned*)Wkh, (const unsigned*)Wvh,
                                          bq, bk, bv, Qd, Kd, Vd);

    attn_tc<<<dim3(SS / QT, BB * HH), 128, attn_smem>>>(
        (const unsigned*)Qd, (const unsigned*)Kd, (const unsigned*)Vd, (unsigned*)Cd);

    dim3 ogrid(DD / 256, MROWS / 128);        // (4, 64)
    gemm_out<<<ogrid, 256, gemm_smem>>>((const unsigned*)Cd, (const unsigned*)Woh, bo, out);
}

// round 15
// speedup vs baseline: 1.0211x; 1.0211x over previous
#include <cuda_runtime.h>
#include <cuda_fp16.h>
#include <math.h>

#define BB 4
#define SS 2048
#define DD 1024
#define HH 16
#define MROWS (BB*SS)   // 8192

// Scratch (device globals). f16 tensors use the "sigma" pair permutation
// within each 64-element k-block (pairs p=8ks+4h+q -> slot q*8+2ks+h).
__device__ __half   g_Qh[BB*SS*DD];   // Q*0.125*log2e, f16 sigma
__device__ __half   g_Kh[BB*SS*DD];   // K, f16 sigma
__device__ __half   g_Vh[BB*SS*DD];   // f16 V^T: [b*H+h][64 d][2048 kv, sigma per 64-tile]
__device__ __half   g_Ch[BB*SS*DD];   // ctx, f16 sigma
__device__ __half   g_Xq[MROWS*DD];
__device__ __half   g_Xk[MROWS*DD];
__device__ __half   g_Xv[MROWS*DD];
__device__ __half   g_Wqh[DD*DD];
__device__ __half   g_Wkh[DD*DD];
__device__ __half   g_Wvh[DD*DD];
__device__ __half   g_Woh[DD*DD];

// ---------------------------------------------------------------------------
// helpers
// ---------------------------------------------------------------------------
__device__ __forceinline__ unsigned packh2(float lo, float hi) {
    __half2 h = __floats2half2_rn(lo, hi);
    return *(unsigned*)&h;
}
__device__ __forceinline__ unsigned ex2h2(unsigned x) {
    unsigned r;
    asm("ex2.approx.f16x2 %0, %1;" : "=r"(r) : "r"(x));
    return r;
}
__device__ __forceinline__ void mma_f16(float* d, const unsigned* a,
                                        const unsigned* b, const float* c) {
    asm volatile(
        "mma.sync.aligned.m16n8k16.row.col.f32.f16.f16.f32 "
        "{%0,%1,%2,%3}, {%4,%5,%6,%7}, {%8,%9}, {%10,%11,%12,%13};\n"
        : "=f"(d[0]), "=f"(d[1]), "=f"(d[2]), "=f"(d[3])
        : "r"(a[0]), "r"(a[1]), "r"(a[2]), "r"(a[3]),
          "r"(b[0]), "r"(b[1]),
          "f"(c[0]), "f"(c[1]), "f"(c[2]), "f"(c[3]));
}
__device__ __forceinline__ void cp16(void* smem, const void* g) {
    unsigned s = (unsigned)__cvta_generic_to_shared(smem);
    asm volatile("cp.async.cg.shared.global [%0], [%1], 16;\n" :: "r"(s), "l"(g));
}
#define CP_COMMIT asm volatile("cp.async.commit_group;\n")
#define CP_WAIT2  asm volatile("cp.async.wait_group 2;\n")
#define CP_WAIT1  asm volatile("cp.async.wait_group 1;\n")
#define CP_WAIT0  asm volatile("cp.async.wait_group 0;\n")

// sigma: pair p = 8ks + 4h + q  ->  slot q*8 + 2ks + h  (u32-pair domain)
__device__ __forceinline__ int sigma(int p) {
    return (p & 3) * 8 + ((p >> 3) << 1) + ((p >> 2) & 1);
}

// ---------------------------------------------------------------------------
// Prep: fp32 -> f16 pairs, sigma-permuted per 64-element block
// ---------------------------------------------------------------------------
__device__ __forceinline__ void cvt_sigma(const float* __restrict__ src,
                                          unsigned* __restrict__ dst) {
    size_t i = ((size_t)blockIdx.x * 256 + threadIdx.x) * 4;
    float4 v = *(const float4*)(src + i);
    size_t base = (i >> 1) & ~(size_t)31;
    int p0 = (int)(i & 63) >> 1;
    dst[base + sigma(p0)    ] = packh2(v.x, v.y);
    dst[base + sigma(p0 + 1)] = packh2(v.z, v.w);
}
__global__ __launch_bounds__(256) void cvt_in(
    const float* __restrict__ a, const float* __restrict__ b,
    const float* __restrict__ c,
    unsigned* __restrict__ oa, unsigned* __restrict__ ob, unsigned* __restrict__ oc)
{
    const float* src = (blockIdx.z == 0) ? a : (blockIdx.z == 1) ? b : c;
    unsigned*    dst = (blockIdx.z == 0) ? oa : (blockIdx.z == 1) ? ob : oc;
    cvt_sigma(src, dst);
}
__global__ __launch_bounds__(256) void cvt_w(
    const float* __restrict__ a, const float* __restrict__ b,
    const float* __restrict__ c, const float* __restrict__ d,
    unsigned* __restrict__ oa, unsigned* __restrict__ ob,
    unsigned* __restrict__ oc, unsigned* __restrict__ od)
{
    const float* src = (blockIdx.z == 0) ? a : (blockIdx.z == 1) ? b
                     : (blockIdx.z == 2) ? c : d;
    unsigned*    dst = (blockIdx.z == 0) ? oa : (blockIdx.z == 1) ? ob
                     : (blockIdx.z == 2) ? oc : od;
    cvt_sigma(src, dst);
}

// ---------------------------------------------------------------------------
// fp16 GEMM v3: warp tile 64x64, CTA tile 128x128, 128 threads (2x2 warps),
// 3-stage cp.async pipeline, 2 CTAs/SM. A fragments cached across the 8
// n-tiles (crossbar ratio 0.75 vs tensor) while independent CTAs cover each
// other's tile boundaries (the occupancy round 14 lost).
// ---------------------------------------------------------------------------
#define GSTR 36
#define ASTG (128 * GSTR)            // u32 per A stage
#define BSTG (128 * GSTR)            // u32 per B stage
#define GSTG (ASTG + BSTG)           // 9216 u32 = 36864 B per stage
template<int PERM>
__device__ __forceinline__ void gemm_body(
    const unsigned* __restrict__ A, const unsigned* __restrict__ W,
    const float* __restrict__ bias, void* __restrict__ Cv,
    int M, int N, int K, float oscale)
{
    extern __shared__ unsigned smu[];

    const int tid  = threadIdx.x;
    const int lane = tid & 31, warp = tid >> 5;   // 4 warps
    const int wy = warp >> 1, wx = warp & 1;      // 2 x 2 warp grid
    const int m0 = wy * 64, n0 = wx * 64;
    const int r = lane >> 2, q = lane & 3;
    const int bm = blockIdx.y * 128, bn = blockIdx.x * 128;
    const int K2 = K >> 1;

    float acc[4][8][4];
    #pragma unroll
    for (int mt = 0; mt < 4; mt++)
        #pragma unroll
        for (int nt = 0; nt < 8; nt++)
            #pragma unroll
            for (int i = 0; i < 4; i++) acc[mt][nt][i] = 0.0f;

    const int NK = K / 64;   // 16

    auto load_stage = [&](int kt, int buf) {
        const unsigned* Ag = A + (size_t)bm * K2 + kt * 32;
        const unsigned* Wg = W + (size_t)bn * K2 + kt * 32;
        unsigned* as = smu + buf * GSTG;
        unsigned* ws = as + ASTG;
        #pragma unroll
        for (int i = 0; i < 8; i++) {               // A: 1024 chunks / 128 thr
            int idx = tid + i * 128;
            int row = idx >> 3, u = idx & 7;
            cp16(&as[row * GSTR + u * 4], Ag + (size_t)row * K2 + u * 4);
        }
        #pragma unroll
        for (int i = 0; i < 8; i++) {               // B: 1024 chunks
            int idx = tid + i * 128;
            int row = idx >> 3, u = idx & 7;
            cp16(&ws[row * GSTR + u * 4], Wg + (size_t)row * K2 + u * 4);
        }
        CP_COMMIT;
    };

    load_stage(0, 0);
    if (NK > 1) load_stage(1, 1);

    for (int kt = 0; kt < NK; kt++) {
        if (kt + 1 < NK) { CP_WAIT1; } else { CP_WAIT0; }
        __syncthreads();
        if (kt + 2 < NK) load_stage(kt + 2, (kt + 2) % 3);

        const unsigned* as = smu + (kt % 3) * GSTG;
        const unsigned* ws = as + ASTG;

        // cache A fragments for all 4 m-tiles (64 regs, reused by 8 n-tiles)
        unsigned af[4][4][4];
        #pragma unroll
        for (int mt = 0; mt < 4; mt++) {
            const uint4* ap0 = (const uint4*)(as + (m0 + mt * 16 + r    ) * GSTR + q * 8);
            const uint4* ap1 = (const uint4*)(as + (m0 + mt * 16 + r + 8) * GSTR + q * 8);
            uint4 a00 = ap0[0], a01 = ap0[1], a10 = ap1[0], a11 = ap1[1];
            unsigned ar0[8] = {a00.x,a00.y,a00.z,a00.w, a01.x,a01.y,a01.z,a01.w};
            unsigned ar1[8] = {a10.x,a10.y,a10.z,a10.w, a11.x,a11.y,a11.z,a11.w};
            #pragma unroll
            for (int ks = 0; ks < 4; ks++) {
                af[mt][ks][0] = ar0[2*ks];
                af[mt][ks][1] = ar1[2*ks];
                af[mt][ks][2] = ar0[2*ks+1];
                af[mt][ks][3] = ar1[2*ks+1];
            }
        }

        #pragma unroll
        for (int nt = 0; nt < 8; nt++) {
            const uint4* bp = (const uint4*)(ws + (n0 + nt * 8 + r) * GSTR + q * 8);
            uint4 u0 = bp[0], u1 = bp[1];
            unsigned bch[8] = {u0.x,u0.y,u0.z,u0.w, u1.x,u1.y,u1.z,u1.w};
            #pragma unroll
            for (int mt = 0; mt < 4; mt++) {
                #pragma unroll
                for (int ks = 0; ks < 4; ks++) {
                    unsigned bf[2] = { bch[2*ks], bch[2*ks+1] };
                    mma_f16(acc[mt][nt], af[mt][ks], bf, acc[mt][nt]);
                }
            }
        }
    }

    if (PERM == 3) {
        __syncthreads();
        // V^T through smem: [128 d][136 tokens] f16, then coalesced sigma write
        __half* Vts = (__half*)smu;
        #pragma unroll
        for (int mt = 0; mt < 4; mt++) {
            #pragma unroll
            for (int nt = 0; nt < 8; nt++) {
                int col = bn + n0 + nt * 8 + 2 * q;
                float2 bv = *(const float2*)&bias[col];
                int tok = m0 + mt * 16 + r;
                int dc  = n0 + nt * 8 + 2 * q;      // local d col 0..127
                Vts[ dc      * 136 + tok    ] = __float2half_rn(acc[mt][nt][0] + bv.x);
                Vts[(dc + 1) * 136 + tok    ] = __float2half_rn(acc[mt][nt][1] + bv.y);
                Vts[ dc      * 136 + tok + 8] = __float2half_rn(acc[mt][nt][2] + bv.x);
                Vts[(dc + 1) * 136 + tok + 8] = __float2half_rn(acc[mt][nt][3] + bv.y);
            }
        }
        __syncthreads();
        const unsigned* Vtu = (const unsigned*)Vts;   // stride 68 u32
        unsigned* Co = (unsigned*)Cv;
        #pragma unroll 4
        for (int i = 0; i < 64; i++) {
            int f = tid + i * 128;                // 128 d x 64 u32 slots
            int d = f >> 6, slot = f & 63;
            int tile = slot >> 5, g = slot & 31;
            int p = ((g >> 1) & 3) * 8 + (g & 1) * 4 + (g >> 3);  // sigma^-1
            unsigned val = Vtu[d * 68 + tile * 32 + p];
            int gc = bn + d;
            int head = gc >> 6, dl = gc & 63;
            int bb = (bm + tile * 64) >> 11;
            int tib = ((bm & 2047) >> 6) + tile;
            Co[((size_t)(bb * HH + head) * 64 + dl) * 1024 + (size_t)tib * 32 + g] = val;
        }
        return;
    }

    #pragma unroll
    for (int mt = 0; mt < 4; mt++) {
        #pragma unroll
        for (int nt = 0; nt < 8; nt++) {
            int col = bn + n0 + nt * 8 + 2 * q;
            float2 bv = *(const float2*)&bias[col];
            int row0 = bm + m0 + mt * 16 + r;
            float v00 = (acc[mt][nt][0] + bv.x) * oscale;
            float v01 = (acc[mt][nt][1] + bv.y) * oscale;
            float v10 = (acc[mt][nt][2] + bv.x) * oscale;
            float v11 = (acc[mt][nt][3] + bv.y) * oscale;
            if (PERM == 0) {
                float* Cf = (float*)Cv;
                *(float2*)&Cf[(size_t)row0     * N + col] = make_float2(v00, v01);
                *(float2*)&Cf[(size_t)(row0+8) * N + col] = make_float2(v10, v11);
            } else {  // PERM 1: f16 sigma
                unsigned* Cu = (unsigned*)Cv;
                int slot = sigma((col & 63) >> 1);
                size_t base = (size_t)row0 * (N >> 1) + ((col >> 6) << 5) + slot;
                Cu[base]                 = packh2(v00, v01);
                Cu[base + 8 * (N >> 1)]  = packh2(v10, v11);
            }
        }
    }
}

__global__ __launch_bounds__(128, 2) void gemm_qkv(
    const unsigned* __restrict__ xq, const unsigned* __restrict__ xk, const unsigned* __restrict__ xv,
    const unsigned* __restrict__ Wq, const unsigned* __restrict__ Wk, const unsigned* __restrict__ Wv,
    const float* __restrict__ bq, const float* __restrict__ bk, const float* __restrict__ bv,
    __half* __restrict__ Qd, __half* __restrict__ Kd, __half* __restrict__ Vd)
{
    const int z = blockIdx.z;
    if      (z == 0) gemm_body<1>(xq, Wq, bq, (void*)Qd, MROWS, DD, DD, 0.18033688f);
    else if (z == 1) gemm_body<1>(xk, Wk, bk, (void*)Kd, MROWS, DD, DD, 1.0f);
    else             gemm_body<3>(xv, Wv, bv, (void*)Vd, MROWS, DD, DD, 1.0f);
}

__global__ __launch_bounds__(128, 2) void gemm_out(
    const unsigned* __restrict__ A, const unsigned* __restrict__ W,
    const float* __restrict__ bias, float* __restrict__ C)
{
    gemm_body<0>(A, W, bias, (void*)C, MROWS, DD, DD, 1.0f);
}

// ---------------------------------------------------------------------------
// fp16 flash attention v13 (unchanged keeper, 173us): 32 q-rows/warp,
// 128-thr CTAs, 3 CTAs/SM, two key-pair passes so pa liveness is 16 regs.
// ---------------------------------------------------------------------------
#define KVSTR 36
#define QT   128
#define KVSTG (2 * 64 * KVSTR)
__global__ __launch_bounds__(128, 3) void attn_tc(
    const unsigned* __restrict__ Q, const unsigned* __restrict__ K,
    const unsigned* __restrict__ V, unsigned* __restrict__ Out)
{
    extern __shared__ unsigned smu[];
    unsigned* Qs = smu + 3 * KVSTG;   // [128][36] u32

    const int tid  = threadIdx.x;
    const int lane = tid & 31, warp = tid >> 5;   // 4 warps
    const int m0 = warp * 32;                     // 32 q-rows per warp
    const int r = lane >> 2, q = lane & 3;
    const int qt = blockIdx.x, bh = blockIdx.y;
    const int b = bh >> 4, h = bh & 15;

    const unsigned* Qg = Q + ((size_t)(b * SS + qt * QT)) * 512 + h * 32;
    const unsigned* Kg = K + ((size_t)(b * SS)) * 512 + h * 32;
    const unsigned* Vg = V + ((size_t)(b * HH + h) * 64) * 1024;

    #pragma unroll
    for (int i = 0; i < 8; i++) {
        int idx = tid + i * 128;
        int row = idx >> 3, u = idx & 7;
        cp16(&Qs[row * KVSTR + u * 4], Qg + (size_t)row * 512 + u * 4);
    }
    CP_COMMIT;

    auto load_stage = [&](int kt, int buf) {
        unsigned* ks_ = smu + buf * KVSTG;
        unsigned* vs_ = ks_ + 64 * KVSTR;
        #pragma unroll
        for (int i = 0; i < 4; i++) {
            int idx = tid + i * 128;
            int row = idx >> 3, u = idx & 7;
            cp16(&ks_[row * KVSTR + u * 4], Kg + (size_t)(kt * 64 + row) * 512 + u * 4);
            cp16(&vs_[row * KVSTR + u * 4], Vg + (size_t)row * 1024 + kt * 32 + u * 4);
        }
        CP_COMMIT;
    };
    load_stage(0, 0);
    load_stage(1, 1);

    CP_WAIT2;          // Q done
    __syncthreads();

    unsigned qa[2][4][4];
    #pragma unroll
    for (int mt = 0; mt < 2; mt++) {
        const uint4* qp0 = (const uint4*)(Qs + (m0 + mt * 16 + r    ) * KVSTR + q * 8);
        const uint4* qp1 = (const uint4*)(Qs + (m0 + mt * 16 + r + 8) * KVSTR + q * 8);
        uint4 a00 = qp0[0], a01 = qp0[1], a10 = qp1[0], a11 = qp1[1];
        unsigned ar0[8] = {a00.x,a00.y,a00.z,a00.w, a01.x,a01.y,a01.z,a01.w};
        unsigned ar1[8] = {a10.x,a10.y,a10.z,a10.w, a11.x,a11.y,a11.z,a11.w};
        #pragma unroll
        for (int ks = 0; ks < 4; ks++) {
            qa[mt][ks][0] = ar0[2*ks];
            qa[mt][ks][1] = ar1[2*ks];
            qa[mt][ks][2] = ar0[2*ks+1];
            qa[mt][ks][3] = ar1[2*ks+1];
        }
    }

    float O[2][8][4];
    #pragma unroll
    for (int mt = 0; mt < 2; mt++)
        #pragma unroll
        for (int nt = 0; nt < 8; nt++)
            #pragma unroll
            for (int i = 0; i < 4; i++) O[mt][nt][i] = 0.0f;
    float Ol[2][4] = {};
    const unsigned onesb[2] = { 0x3C003C00u, 0x3C003C00u };

    const int NT = SS / 64;
    for (int kt = 0; kt < NT; kt++) {
        if (kt + 1 < NT) { CP_WAIT1; } else { CP_WAIT0; }
        __syncthreads();
        if (kt + 2 < NT) load_stage(kt + 2, (kt + 2) % 3);

        const unsigned* Ks = smu + (kt % 3) * KVSTG;
        const unsigned* Vs = Ks + 64 * KVSTR;

        #pragma unroll
        for (int tp = 0; tp < 2; tp++) {
            unsigned pa[2][2][4];
            #pragma unroll
            for (int ntl = 0; ntl < 4; ntl++) {
                int nt = tp * 4 + ntl;
                const uint4* kp = (const uint4*)(Ks + (nt * 8 + r) * KVSTR + q * 8);
                uint4 u0 = kp[0], u1 = kp[1];
                unsigned ch[8] = {u0.x,u0.y,u0.z,u0.w, u1.x,u1.y,u1.z,u1.w};
                float sf0[4] = {0,0,0,0}, sf1[4] = {0,0,0,0};
                #pragma unroll
                for (int ks = 0; ks < 4; ks++) {
                    unsigned bf[2] = { ch[2*ks], ch[2*ks+1] };
                    mma_f16(sf0, qa[0][ks], bf, sf0);
                    mma_f16(sf1, qa[1][ks], bf, sf1);
                }
                int tl = ntl >> 1, j = ntl & 1;
                pa[0][tl][2*j    ] = ex2h2(packh2(sf0[0], sf0[1]));
                pa[0][tl][2*j + 1] = ex2h2(packh2(sf0[2], sf0[3]));
                pa[1][tl][2*j    ] = ex2h2(packh2(sf1[0], sf1[1]));
                pa[1][tl][2*j + 1] = ex2h2(packh2(sf1[2], sf1[3]));
            }

            #pragma unroll
            for (int tl = 0; tl < 2; tl++) {
                mma_f16(Ol[0], pa[0][tl], onesb, Ol[0]);
                mma_f16(Ol[1], pa[1][tl], onesb, Ol[1]);
            }

            #pragma unroll
            for (int nt = 0; nt < 8; nt++) {
                uint4 v = *(const uint4*)(Vs + (nt * 8 + r) * KVSTR + q * 8 + tp * 4);
                unsigned bf0[2] = { v.x, v.y };
                unsigned bf1[2] = { v.z, v.w };
                mma_f16(O[0][nt], pa[0][0], bf0, O[0][nt]);
                mma_f16(O[0][nt], pa[0][1], bf1, O[0][nt]);
                mma_f16(O[1][nt], pa[1][0], bf0, O[1][nt]);
                mma_f16(O[1][nt], pa[1][1], bf1, O[1][nt]);
            }
        }
    }

    unsigned* Og = Out + ((size_t)(b * SS + qt * QT)) * 512 + h * 32;
    #pragma unroll
    for (int mt = 0; mt < 2; mt++) {
        float inv0 = 1.0f / Ol[mt][0], inv1 = 1.0f / Ol[mt][2];
        #pragma unroll
        for (int nt = 0; nt < 8; nt++) {
            int c0 = nt * 8 + 2 * q;
            int slot = sigma(c0 >> 1);
            size_t ra = (size_t)(m0 + mt * 16 + r    ) * 512;
            size_t rb = (size_t)(m0 + mt * 16 + r + 8) * 512;
            Og[ra + slot] = packh2(O[mt][nt][0] * inv0, O[mt][nt][1] * inv0);
            Og[rb + slot] = packh2(O[mt][nt][2] * inv1, O[mt][nt][3] * inv1);
        }
    }
}

// ---------------------------------------------------------------------------
extern "C" void kernel_launch(void* const* d_in, const int* in_sizes, int n_in,
                              void* d_out, int out_size)
{
    const float* query = (const float*)d_in[0];
    const float* key_  = (const float*)d_in[1];
    const float* value = (const float*)d_in[2];
    const float* Wq    = (const float*)d_in[3];
    const float* bq    = (const float*)d_in[4];
    const float* Wk    = (const float*)d_in[5];
    const float* bk    = (const float*)d_in[6];
    const float* Wv    = (const float*)d_in[7];
    const float* bv    = (const float*)d_in[8];
    const float* Wo    = (const float*)d_in[9];
    const float* bo    = (const float*)d_in[10];
    float* out = (float*)d_out;

    __half *Qd, *Kd, *Vd, *Cd, *Xq, *Xk, *Xv, *Wqh, *Wkh, *Wvh, *Woh;
    cudaGetSymbolAddress((void**)&Qd,  g_Qh);
    cudaGetSymbolAddress((void**)&Kd,  g_Kh);
    cudaGetSymbolAddress((void**)&Vd,  g_Vh);
    cudaGetSymbolAddress((void**)&Cd,  g_Ch);
    cudaGetSymbolAddress((void**)&Xq,  g_Xq);
    cudaGetSymbolAddress((void**)&Xk,  g_Xk);
    cudaGetSymbolAddress((void**)&Xv,  g_Xv);
    cudaGetSymbolAddress((void**)&Wqh, g_Wqh);
    cudaGetSymbolAddress((void**)&Wkh, g_Wkh);
    cudaGetSymbolAddress((void**)&Wvh, g_Wvh);
    cudaGetSymbolAddress((void**)&Woh, g_Woh);

    const int gemm_smem = 3 * GSTG * 4;                         // 110592
    const int attn_smem = (3 * KVSTG + QT * KVSTR) * 4;         // 73728
    cudaFuncSetAttribute(gemm_qkv, cudaFuncAttributeMaxDynamicSharedMemorySize, gemm_smem);
    cudaFuncSetAttribute(gemm_out, cudaFuncAttributeMaxDynamicSharedMemorySize, gemm_smem);
    cudaFuncSetAttribute(attn_tc,  cudaFuncAttributeMaxDynamicSharedMemorySize, attn_smem);

    cvt_in<<<dim3(MROWS*DD/4/256, 1, 3), 256>>>(query, key_, value,
                                                (unsigned*)Xq, (unsigned*)Xk, (unsigned*)Xv);
    cvt_w <<<dim3(DD*DD/4/256,   1, 4), 256>>>(Wq, Wk, Wv, Wo,
                                               (unsigned*)Wqh, (unsigned*)Wkh,
                                               (unsigned*)Wvh, (unsigned*)Woh);

    dim3 qkvgrid(DD / 128, MROWS / 128, 3);   // (8, 64, 3)
    gemm_qkv<<<qkvgrid, 128, gemm_smem>>>((const unsigned*)Xq, (const unsigned*)Xk,
                                          (const unsigned*)Xv, (const unsigned*)Wqh,
                                          (const unsigned*)Wkh, (const unsigned*)Wvh,
                                          bq, bk, bv, Qd, Kd, Vd);

    attn_tc<<<dim3(SS / QT, BB * HH), 128, attn_smem>>>(
        (const unsigned*)Qd, (const unsigned*)Kd, (const unsigned*)Vd, (unsigned*)Cd);

    dim3 ogrid(DD / 128, MROWS / 128);        // (8, 64)
    gemm_out<<<ogrid, 128, gemm_smem>>>((const unsigned*)Cd, (const unsigned*)Woh, bo, out);
}

// round 16
// speedup vs baseline: 1.1057x; 1.0828x over previous
#include <cuda_runtime.h>
#include <cuda_fp16.h>
#include <math.h>

#define BB 4
#define SS 2048
#define DD 1024
#define HH 16
#define MROWS (BB*SS)   // 8192

// Scratch (device globals). f16 tensors use the "sigma" pair permutation
// within each 64-element k-block (pairs p=8ks+4h+q -> slot q*8+2ks+h).
__device__ __half   g_Qh[BB*SS*DD];   // Q*0.125*log2e, f16 sigma
__device__ __half   g_Kh[BB*SS*DD];   // K, f16 sigma
__device__ __half   g_Vh[BB*SS*DD];   // f16 V^T: [b*H+h][64 d][2048 kv, sigma per 64-tile]
__device__ __half   g_Ch[BB*SS*DD];   // ctx, f16 sigma
__device__ __half   g_Xq[MROWS*DD];
__device__ __half   g_Xk[MROWS*DD];
__device__ __half   g_Xv[MROWS*DD];
__device__ __half   g_Wqh[DD*DD];
__device__ __half   g_Wkh[DD*DD];
__device__ __half   g_Wvh[DD*DD];
__device__ __half   g_Woh[DD*DD];

// ---------------------------------------------------------------------------
// helpers
// ---------------------------------------------------------------------------
__device__ __forceinline__ unsigned packh2(float lo, float hi) {
    __half2 h = __floats2half2_rn(lo, hi);
    return *(unsigned*)&h;
}
__device__ __forceinline__ unsigned ex2h2(unsigned x) {
    unsigned r;
    asm("ex2.approx.f16x2 %0, %1;" : "=r"(r) : "r"(x));
    return r;
}
__device__ __forceinline__ void mma_f16(float* d, const unsigned* a,
                                        const unsigned* b, const float* c) {
    asm volatile(
        "mma.sync.aligned.m16n8k16.row.col.f32.f16.f16.f32 "
        "{%0,%1,%2,%3}, {%4,%5,%6,%7}, {%8,%9}, {%10,%11,%12,%13};\n"
        : "=f"(d[0]), "=f"(d[1]), "=f"(d[2]), "=f"(d[3])
        : "r"(a[0]), "r"(a[1]), "r"(a[2]), "r"(a[3]),
          "r"(b[0]), "r"(b[1]),
          "f"(c[0]), "f"(c[1]), "f"(c[2]), "f"(c[3]));
}
__device__ __forceinline__ void cp16(void* smem, const void* g) {
    unsigned s = (unsigned)__cvta_generic_to_shared(smem);
    asm volatile("cp.async.cg.shared.global [%0], [%1], 16;\n" :: "r"(s), "l"(g));
}
#define CP_COMMIT asm volatile("cp.async.commit_group;\n")
#define CP_WAIT2  asm volatile("cp.async.wait_group 2;\n")
#define CP_WAIT1  asm volatile("cp.async.wait_group 1;\n")
#define CP_WAIT0  asm volatile("cp.async.wait_group 0;\n")

// sigma: pair p = 8ks + 4h + q  ->  slot q*8 + 2ks + h  (u32-pair domain)
__device__ __forceinline__ int sigma(int p) {
    return (p & 3) * 8 + ((p >> 3) << 1) + ((p >> 2) & 1);
}

// ---------------------------------------------------------------------------
// Prep: single fused launch. fp32 -> f16 pairs, sigma-permuted per 64 block.
// Blocks [0, 24576): the 3 activation tensors (8192 blocks each).
// Blocks [24576, 28672): the 4 weight matrices (1024 blocks each).
// ---------------------------------------------------------------------------
__global__ __launch_bounds__(256) void cvt_all(
    const float* __restrict__ xq, const float* __restrict__ xk,
    const float* __restrict__ xv,
    const float* __restrict__ wq, const float* __restrict__ wk,
    const float* __restrict__ wv, const float* __restrict__ wo,
    unsigned* __restrict__ oq, unsigned* __restrict__ ok, unsigned* __restrict__ ov,
    unsigned* __restrict__ owq, unsigned* __restrict__ owk,
    unsigned* __restrict__ owv, unsigned* __restrict__ owo)
{
    int bid = blockIdx.x;
    const float* src;
    unsigned* dst;
    size_t lb;
    if (bid < 24576) {
        int t = bid >> 13;              // / 8192
        lb = (size_t)(bid & 8191);
        src = (t == 0) ? xq : (t == 1) ? xk : xv;
        dst = (t == 0) ? oq : (t == 1) ? ok : ov;
    } else {
        int wb = bid - 24576;
        int t = wb >> 10;               // / 1024
        lb = (size_t)(wb & 1023);
        src = (t == 0) ? wq : (t == 1) ? wk : (t == 2) ? wv : wo;
        dst = (t == 0) ? owq : (t == 1) ? owk : (t == 2) ? owv : owo;
    }
    size_t i = (lb * 256 + threadIdx.x) * 4;
    float4 v = *(const float4*)(src + i);
    size_t base = (i >> 1) & ~(size_t)31;
    int p0 = (int)(i & 63) >> 1;
    dst[base + sigma(p0)    ] = packh2(v.x, v.y);
    dst[base + sigma(p0 + 1)] = packh2(v.z, v.w);
}

// ---------------------------------------------------------------------------
// fp16 tensor-core GEMM v1 (round-13 keeper): warp tile 64x32, 256 thr
// (8 warps, 2x4), 3-stage cp.async pipeline, 2 CTAs/SM = 4 warps/SMSP.
// ---------------------------------------------------------------------------
#define GSTR 36
#define GSTG (128 * GSTR)
template<int PERM>
__device__ __forceinline__ void gemm_body(
    const unsigned* __restrict__ A, const unsigned* __restrict__ W,
    const float* __restrict__ bias, void* __restrict__ Cv,
    int M, int N, int K, float oscale)
{
    extern __shared__ unsigned smu[];

    const int tid  = threadIdx.x;
    const int lane = tid & 31, warp = tid >> 5;
    const int wy = warp >> 2, wx = warp & 3;
    const int m0 = wy * 64, n0 = wx * 32;
    const int r = lane >> 2, q = lane & 3;
    const int bm = blockIdx.y * 128, bn = blockIdx.x * 128;
    const int K2 = K >> 1;

    float acc[4][4][4];
    #pragma unroll
    for (int mt = 0; mt < 4; mt++)
        #pragma unroll
        for (int nt = 0; nt < 4; nt++)
            #pragma unroll
            for (int i = 0; i < 4; i++) acc[mt][nt][i] = 0.0f;

    const int NK = K / 64;

    auto load_stage = [&](int kt, int buf) {
        const unsigned* Ag = A + (size_t)bm * K2 + kt * 32;
        const unsigned* Wg = W + (size_t)bn * K2 + kt * 32;
        unsigned* as = smu + buf * 2 * GSTG;
        unsigned* ws = as + GSTG;
        #pragma unroll
        for (int i = 0; i < 4; i++) {
            int idx = tid + i * 256;
            int row = idx >> 3, u = idx & 7;
            cp16(&as[row * GSTR + u * 4], Ag + (size_t)row * K2 + u * 4);
            cp16(&ws[row * GSTR + u * 4], Wg + (size_t)row * K2 + u * 4);
        }
        CP_COMMIT;
    };

    load_stage(0, 0);
    if (NK > 1) load_stage(1, 1);

    for (int kt = 0; kt < NK; kt++) {
        if (kt + 1 < NK) { CP_WAIT1; } else { CP_WAIT0; }
        __syncthreads();
        if (kt + 2 < NK) load_stage(kt + 2, (kt + 2) % 3);

        const unsigned* as = smu + (kt % 3) * 2 * GSTG;
        const unsigned* ws = as + GSTG;

        unsigned bch[4][8];
        #pragma unroll
        for (int nt = 0; nt < 4; nt++) {
            const uint4* bp = (const uint4*)(ws + (n0 + nt * 8 + r) * GSTR + q * 8);
            uint4 u0 = bp[0], u1 = bp[1];
            bch[nt][0]=u0.x; bch[nt][1]=u0.y; bch[nt][2]=u0.z; bch[nt][3]=u0.w;
            bch[nt][4]=u1.x; bch[nt][5]=u1.y; bch[nt][6]=u1.z; bch[nt][7]=u1.w;
        }

        #pragma unroll
        for (int mt = 0; mt < 4; mt++) {
            const uint4* ap0 = (const uint4*)(as + (m0 + mt * 16 + r    ) * GSTR + q * 8);
            const uint4* ap1 = (const uint4*)(as + (m0 + mt * 16 + r + 8) * GSTR + q * 8);
            uint4 a00 = ap0[0], a01 = ap0[1], a10 = ap1[0], a11 = ap1[1];
            unsigned ar0[8] = {a00.x,a00.y,a00.z,a00.w, a01.x,a01.y,a01.z,a01.w};
            unsigned ar1[8] = {a10.x,a10.y,a10.z,a10.w, a11.x,a11.y,a11.z,a11.w};
            #pragma unroll
            for (int nt = 0; nt < 4; nt++) {
                #pragma unroll
                for (int ks = 0; ks < 4; ks++) {
                    unsigned af[4] = { ar0[2*ks], ar1[2*ks], ar0[2*ks+1], ar1[2*ks+1] };
                    unsigned bf[2] = { bch[nt][2*ks], bch[nt][2*ks+1] };
                    mma_f16(acc[mt][nt], af, bf, acc[mt][nt]);
                }
            }
        }
    }

    if (PERM == 3) {
        __syncthreads();
        __half* Vts = (__half*)smu;
        #pragma unroll
        for (int mt = 0; mt < 4; mt++) {
            #pragma unroll
            for (int nt = 0; nt < 4; nt++) {
                int col = bn + n0 + nt * 8 + 2 * q;
                float2 bv = *(const float2*)&bias[col];
                int tok = m0 + mt * 16 + r;
                int dc  = n0 + nt * 8 + 2 * q;
                Vts[ dc      * 136 + tok    ] = __float2half_rn(acc[mt][nt][0] + bv.x);
                Vts[(dc + 1) * 136 + tok    ] = __float2half_rn(acc[mt][nt][1] + bv.y);
                Vts[ dc      * 136 + tok + 8] = __float2half_rn(acc[mt][nt][2] + bv.x);
                Vts[(dc + 1) * 136 + tok + 8] = __float2half_rn(acc[mt][nt][3] + bv.y);
            }
        }
        __syncthreads();
        const unsigned* Vtu = (const unsigned*)Vts;
        unsigned* Co = (unsigned*)Cv;
        for (int f = tid; f < 128 * 64; f += 256) {
            int d = f >> 6, slot = f & 63;
            int tile = slot >> 5, g = slot & 31;
            int p = ((g >> 1) & 3) * 8 + (g & 1) * 4 + (g >> 3);  // sigma^-1
            unsigned val = Vtu[d * 68 + tile * 32 + p];
            int gc = bn + d;
            int head = gc >> 6, dl = gc & 63;
            int bb = (bm + tile * 64) >> 11;
            int tib = ((bm & 2047) >> 6) + tile;
            Co[((size_t)(bb * HH + head) * 64 + dl) * 1024 + (size_t)tib * 32 + g] = val;
        }
        return;
    }

    #pragma unroll
    for (int mt = 0; mt < 4; mt++) {
        #pragma unroll
        for (int nt = 0; nt < 4; nt++) {
            int col = bn + n0 + nt * 8 + 2 * q;
            float2 bv = *(const float2*)&bias[col];
            int row0 = bm + m0 + mt * 16 + r;
            float v00 = (acc[mt][nt][0] + bv.x) * oscale;
            float v01 = (acc[mt][nt][1] + bv.y) * oscale;
            float v10 = (acc[mt][nt][2] + bv.x) * oscale;
            float v11 = (acc[mt][nt][3] + bv.y) * oscale;
            if (PERM == 0) {
                float* Cf = (float*)Cv;
                *(float2*)&Cf[(size_t)row0     * N + col] = make_float2(v00, v01);
                *(float2*)&Cf[(size_t)(row0+8) * N + col] = make_float2(v10, v11);
            } else {
                unsigned* Cu = (unsigned*)Cv;
                int slot = sigma((col & 63) >> 1);
                size_t base = (size_t)row0 * (N >> 1) + ((col >> 6) << 5) + slot;
                Cu[base]                 = packh2(v00, v01);
                Cu[base + 8 * (N >> 1)]  = packh2(v10, v11);
            }
        }
    }
}

__global__ __launch_bounds__(256, 2) void gemm_qkv(
    const unsigned* __restrict__ xq, const unsigned* __restrict__ xk, const unsigned* __restrict__ xv,
    const unsigned* __restrict__ Wq, const unsigned* __restrict__ Wk, const unsigned* __restrict__ Wv,
    const float* __restrict__ bq, const float* __restrict__ bk, const float* __restrict__ bv,
    __half* __restrict__ Qd, __half* __restrict__ Kd, __half* __restrict__ Vd)
{
    const int z = blockIdx.z;
    if      (z == 0) gemm_body<1>(xq, Wq, bq, (void*)Qd, MROWS, DD, DD, 0.18033688f);
    else if (z == 1) gemm_body<1>(xk, Wk, bk, (void*)Kd, MROWS, DD, DD, 1.0f);
    else             gemm_body<3>(xv, Wv, bv, (void*)Vd, MROWS, DD, DD, 1.0f);
}

__global__ __launch_bounds__(256, 2) void gemm_out(
    const unsigned* __restrict__ A, const unsigned* __restrict__ W,
    const float* __restrict__ bias, float* __restrict__ C)
{
    gemm_body<0>(A, W, bias, (void*)C, MROWS, DD, DD, 1.0f);
}

// ---------------------------------------------------------------------------
// fp16 flash attention v13 (keeper): 32 q-rows/warp, 128-thr CTAs, 3 CTAs/SM,
// two key-pair passes per tile so pa liveness stays at 16 regs.
// ---------------------------------------------------------------------------
#define KVSTR 36
#define QT   128
#define KVSTG (2 * 64 * KVSTR)
__global__ __launch_bounds__(128, 3) void attn_tc(
    const unsigned* __restrict__ Q, const unsigned* __restrict__ K,
    const unsigned* __restrict__ V, unsigned* __restrict__ Out)
{
    extern __shared__ unsigned smu[];
    unsigned* Qs = smu + 3 * KVSTG;   // [128][36] u32

    const int tid  = threadIdx.x;
    const int lane = tid & 31, warp = tid >> 5;   // 4 warps
    const int m0 = warp * 32;                     // 32 q-rows per warp
    const int r = lane >> 2, q = lane & 3;
    const int qt = blockIdx.x, bh = blockIdx.y;
    const int b = bh >> 4, h = bh & 15;

    const unsigned* Qg = Q + ((size_t)(b * SS + qt * QT)) * 512 + h * 32;
    const unsigned* Kg = K + ((size_t)(b * SS)) * 512 + h * 32;
    const unsigned* Vg = V + ((size_t)(b * HH + h) * 64) * 1024;

    #pragma unroll
    for (int i = 0; i < 8; i++) {
        int idx = tid + i * 128;
        int row = idx >> 3, u = idx & 7;
        cp16(&Qs[row * KVSTR + u * 4], Qg + (size_t)row * 512 + u * 4);
    }
    CP_COMMIT;

    auto load_stage = [&](int kt, int buf) {
        unsigned* ks_ = smu + buf * KVSTG;
        unsigned* vs_ = ks_ + 64 * KVSTR;
        #pragma unroll
        for (int i = 0; i < 4; i++) {
            int idx = tid + i * 128;
            int row = idx >> 3, u = idx & 7;
            cp16(&ks_[row * KVSTR + u * 4], Kg + (size_t)(kt * 64 + row) * 512 + u * 4);
            cp16(&vs_[row * KVSTR + u * 4], Vg + (size_t)row * 1024 + kt * 32 + u * 4);
        }
        CP_COMMIT;
    };
    load_stage(0, 0);
    load_stage(1, 1);

    CP_WAIT2;          // Q done
    __syncthreads();

    unsigned qa[2][4][4];
    #pragma unroll
    for (int mt = 0; mt < 2; mt++) {
        const uint4* qp0 = (const uint4*)(Qs + (m0 + mt * 16 + r    ) * KVSTR + q * 8);
        const uint4* qp1 = (const uint4*)(Qs + (m0 + mt * 16 + r + 8) * KVSTR + q * 8);
        uint4 a00 = qp0[0], a01 = qp0[1], a10 = qp1[0], a11 = qp1[1];
        unsigned ar0[8] = {a00.x,a00.y,a00.z,a00.w, a01.x,a01.y,a01.z,a01.w};
        unsigned ar1[8] = {a10.x,a10.y,a10.z,a10.w, a11.x,a11.y,a11.z,a11.w};
        #pragma unroll
        for (int ks = 0; ks < 4; ks++) {
            qa[mt][ks][0] = ar0[2*ks];
            qa[mt][ks][1] = ar1[2*ks];
            qa[mt][ks][2] = ar0[2*ks+1];
            qa[mt][ks][3] = ar1[2*ks+1];
        }
    }

    float O[2][8][4];
    #pragma unroll
    for (int mt = 0; mt < 2; mt++)
        #pragma unroll
        for (int nt = 0; nt < 8; nt++)
            #pragma unroll
            for (int i = 0; i < 4; i++) O[mt][nt][i] = 0.0f;
    float Ol[2][4] = {};
    const unsigned onesb[2] = { 0x3C003C00u, 0x3C003C00u };

    const int NT = SS / 64;
    for (int kt = 0; kt < NT; kt++) {
        if (kt + 1 < NT) { CP_WAIT1; } else { CP_WAIT0; }
        __syncthreads();
        if (kt + 2 < NT) load_stage(kt + 2, (kt + 2) % 3);

        const unsigned* Ks = smu + (kt % 3) * KVSTG;
        const unsigned* Vs = Ks + 64 * KVSTR;

        #pragma unroll
        for (int tp = 0; tp < 2; tp++) {
            unsigned pa[2][2][4];
            #pragma unroll
            for (int ntl = 0; ntl < 4; ntl++) {
                int nt = tp * 4 + ntl;
                const uint4* kp = (const uint4*)(Ks + (nt * 8 + r) * KVSTR + q * 8);
                uint4 u0 = kp[0], u1 = kp[1];
                unsigned ch[8] = {u0.x,u0.y,u0.z,u0.w, u1.x,u1.y,u1.z,u1.w};
                float sf0[4] = {0,0,0,0}, sf1[4] = {0,0,0,0};
                #pragma unroll
                for (int ks = 0; ks < 4; ks++) {
                    unsigned bf[2] = { ch[2*ks], ch[2*ks+1] };
                    mma_f16(sf0, qa[0][ks], bf, sf0);
                    mma_f16(sf1, qa[1][ks], bf, sf1);
                }
                int tl = ntl >> 1, j = ntl & 1;
                pa[0][tl][2*j    ] = ex2h2(packh2(sf0[0], sf0[1]));
                pa[0][tl][2*j + 1] = ex2h2(packh2(sf0[2], sf0[3]));
                pa[1][tl][2*j    ] = ex2h2(packh2(sf1[0], sf1[1]));
                pa[1][tl][2*j + 1] = ex2h2(packh2(sf1[2], sf1[3]));
            }

            #pragma unroll
            for (int tl = 0; tl < 2; tl++) {
                mma_f16(Ol[0], pa[0][tl], onesb, Ol[0]);
                mma_f16(Ol[1], pa[1][tl], onesb, Ol[1]);
            }

            #pragma unroll
            for (int nt = 0; nt < 8; nt++) {
                uint4 v = *(const uint4*)(Vs + (nt * 8 + r) * KVSTR + q * 8 + tp * 4);
                unsigned bf0[2] = { v.x, v.y };
                unsigned bf1[2] = { v.z, v.w };
                mma_f16(O[0][nt], pa[0][0], bf0, O[0][nt]);
                mma_f16(O[0][nt], pa[0][1], bf1, O[0][nt]);
                mma_f16(O[1][nt], pa[1][0], bf0, O[1][nt]);
                mma_f16(O[1][nt], pa[1][1], bf1, O[1][nt]);
            }
        }
    }

    unsigned* Og = Out + ((size_t)(b * SS + qt * QT)) * 512 + h * 32;
    #pragma unroll
    for (int mt = 0; mt < 2; mt++) {
        float inv0 = 1.0f / Ol[mt][0], inv1 = 1.0f / Ol[mt][2];
        #pragma unroll
        for (int nt = 0; nt < 8; nt++) {
            int c0 = nt * 8 + 2 * q;
            int slot = sigma(c0 >> 1);
            size_t ra = (size_t)(m0 + mt * 16 + r    ) * 512;
            size_t rb = (size_t)(m0 + mt * 16 + r + 8) * 512;
            Og[ra + slot] = packh2(O[mt][nt][0] * inv0, O[mt][nt][1] * inv0);
            Og[rb + slot] = packh2(O[mt][nt][2] * inv1, O[mt][nt][3] * inv1);
        }
    }
}

// ---------------------------------------------------------------------------
extern "C" void kernel_launch(void* const* d_in, const int* in_sizes, int n_in,
                              void* d_out, int out_size)
{
    const float* query = (const float*)d_in[0];
    const float* key_  = (const float*)d_in[1];
    const float* value = (const float*)d_in[2];
    const float* Wq    = (const float*)d_in[3];
    const float* bq    = (const float*)d_in[4];
    const float* Wk    = (const float*)d_in[5];
    const float* bk    = (const float*)d_in[6];
    const float* Wv    = (const float*)d_in[7];
    const float* bv    = (const float*)d_in[8];
    const float* Wo    = (const float*)d_in[9];
    const float* bo    = (const float*)d_in[10];
    float* out = (float*)d_out;

    __half *Qd, *Kd, *Vd, *Cd, *Xq, *Xk, *Xv, *Wqh, *Wkh, *Wvh, *Woh;
    cudaGetSymbolAddress((void**)&Qd,  g_Qh);
    cudaGetSymbolAddress((void**)&Kd,  g_Kh);
    cudaGetSymbolAddress((void**)&Vd,  g_Vh);
    cudaGetSymbolAddress((void**)&Cd,  g_Ch);
    cudaGetSymbolAddress((void**)&Xq,  g_Xq);
    cudaGetSymbolAddress((void**)&Xk,  g_Xk);
    cudaGetSymbolAddress((void**)&Xv,  g_Xv);
    cudaGetSymbolAddress((void**)&Wqh, g_Wqh);
    cudaGetSymbolAddress((void**)&Wkh, g_Wkh);
    cudaGetSymbolAddress((void**)&Wvh, g_Wvh);
    cudaGetSymbolAddress((void**)&Woh, g_Woh);

    const int gemm_smem = 3 * 2 * GSTG * 4;                     // 110592
    const int attn_smem = (3 * KVSTG + QT * KVSTR) * 4;         // 73728
    cudaFuncSetAttribute(gemm_qkv, cudaFuncAttributeMaxDynamicSharedMemorySize, gemm_smem);
    cudaFuncSetAttribute(gemm_out, cudaFuncAttributeMaxDynamicSharedMemorySize, gemm_smem);
    cudaFuncSetAttribute(attn_tc,  cudaFuncAttributeMaxDynamicSharedMemorySize, attn_smem);

    // fused conversion: 3 activation tensors + 4 weight matrices, one launch
    cvt_all<<<28672, 256>>>(query, key_, value, Wq, Wk, Wv, Wo,
                            (unsigned*)Xq, (unsigned*)Xk, (unsigned*)Xv,
                            (unsigned*)Wqh, (unsigned*)Wkh,
                            (unsigned*)Wvh, (unsigned*)Woh);

    dim3 qkvgrid(DD / 128, MROWS / 128, 3);   // (8, 64, 3)
    gemm_qkv<<<qkvgrid, 256, gemm_smem>>>((const unsigned*)Xq, (const unsigned*)Xk,
                                          (const unsigned*)Xv, (const unsigned*)Wqh,
                                          (const unsigned*)Wkh, (const unsigned*)Wvh,
                                          bq, bk, bv, Qd, Kd, Vd);

    attn_tc<<<dim3(SS / QT, BB * HH), 128, attn_smem>>>(
        (const unsigned*)Qd, (const unsigned*)Kd, (const unsigned*)Vd, (unsigned*)Cd);

    dim3 ogrid(DD / 128, MROWS / 128);        // (8, 64)
    gemm_out<<<ogrid, 256, gemm_smem>>>((const unsigned*)Cd, (const unsigned*)Woh, bo, out);
}

// round 17
// speedup vs baseline: 1.1122x; 1.0058x over previous
#include <cuda_runtime.h>
#include <cuda_fp16.h>
#include <math.h>

#define BB 4
#define SS 2048
#define DD 1024
#define HH 16
#define MROWS (BB*SS)   // 8192

// Scratch (device globals). f16 tensors use the "sigma" pair permutation
// within each 64-element k-block (pairs p=8ks+4h+q -> slot q*8+2ks+h).
__device__ __half   g_Qh[BB*SS*DD];   // Q*0.125*log2e, f16 sigma
__device__ __half   g_Kh[BB*SS*DD];   // K, f16 sigma
__device__ __half   g_Vh[BB*SS*DD];   // f16 V^T: [b*H+h][64 d][2048 kv, sigma per 64-tile]
__device__ __half   g_Ch[BB*SS*DD];   // ctx, f16 sigma
__device__ __half   g_Xq[MROWS*DD];
__device__ __half   g_Xk[MROWS*DD];
__device__ __half   g_Xv[MROWS*DD];
__device__ __half   g_Wqh[DD*DD];
__device__ __half   g_Wkh[DD*DD];
__device__ __half   g_Wvh[DD*DD];
__device__ __half   g_Woh[DD*DD];

// ---------------------------------------------------------------------------
// helpers
// ---------------------------------------------------------------------------
__device__ __forceinline__ unsigned packh2(float lo, float hi) {
    __half2 h = __floats2half2_rn(lo, hi);
    return *(unsigned*)&h;
}
__device__ __forceinline__ unsigned ex2h2(unsigned x) {
    unsigned r;
    asm("ex2.approx.f16x2 %0, %1;" : "=r"(r) : "r"(x));
    return r;
}
__device__ __forceinline__ void mma_f16(float* d, const unsigned* a,
                                        const unsigned* b, const float* c) {
    asm volatile(
        "mma.sync.aligned.m16n8k16.row.col.f32.f16.f16.f32 "
        "{%0,%1,%2,%3}, {%4,%5,%6,%7}, {%8,%9}, {%10,%11,%12,%13};\n"
        : "=f"(d[0]), "=f"(d[1]), "=f"(d[2]), "=f"(d[3])
        : "r"(a[0]), "r"(a[1]), "r"(a[2]), "r"(a[3]),
          "r"(b[0]), "r"(b[1]),
          "f"(c[0]), "f"(c[1]), "f"(c[2]), "f"(c[3]));
}
// f16-accumulator variant: D/C are 2 packed b32 regs. C fragment layout:
// c0 = {(r, 2q) lo, (r, 2q+1) hi}, c1 = {(r+8, 2q), (r+8, 2q+1)} — exactly
// the ex2h2 input we need (replaces packh2 of fp32 lanes).
__device__ __forceinline__ void mma_f16c16(unsigned* d, const unsigned* a,
                                           const unsigned* b, const unsigned* c) {
    asm volatile(
        "mma.sync.aligned.m16n8k16.row.col.f16.f16.f16.f16 "
        "{%0,%1}, {%2,%3,%4,%5}, {%6,%7}, {%8,%9};\n"
        : "=r"(d[0]), "=r"(d[1])
        : "r"(a[0]), "r"(a[1]), "r"(a[2]), "r"(a[3]),
          "r"(b[0]), "r"(b[1]),
          "r"(c[0]), "r"(c[1]));
}
__device__ __forceinline__ void cp16(void* smem, const void* g) {
    unsigned s = (unsigned)__cvta_generic_to_shared(smem);
    asm volatile("cp.async.cg.shared.global [%0], [%1], 16;\n" :: "r"(s), "l"(g));
}
#define CP_COMMIT asm volatile("cp.async.commit_group;\n")
#define CP_WAIT2  asm volatile("cp.async.wait_group 2;\n")
#define CP_WAIT1  asm volatile("cp.async.wait_group 1;\n")
#define CP_WAIT0  asm volatile("cp.async.wait_group 0;\n")

// sigma: pair p = 8ks + 4h + q  ->  slot q*8 + 2ks + h  (u32-pair domain)
__device__ __forceinline__ int sigma(int p) {
    return (p & 3) * 8 + ((p >> 3) << 1) + ((p >> 2) & 1);
}

// ---------------------------------------------------------------------------
// Prep: single fused launch. fp32 -> f16 pairs, sigma-permuted per 64 block.
// ---------------------------------------------------------------------------
__global__ __launch_bounds__(256) void cvt_all(
    const float* __restrict__ xq, const float* __restrict__ xk,
    const float* __restrict__ xv,
    const float* __restrict__ wq, const float* __restrict__ wk,
    const float* __restrict__ wv, const float* __restrict__ wo,
    unsigned* __restrict__ oq, unsigned* __restrict__ ok, unsigned* __restrict__ ov,
    unsigned* __restrict__ owq, unsigned* __restrict__ owk,
    unsigned* __restrict__ owv, unsigned* __restrict__ owo)
{
    int bid = blockIdx.x;
    const float* src;
    unsigned* dst;
    size_t lb;
    if (bid < 24576) {
        int t = bid >> 13;
        lb = (size_t)(bid & 8191);
        src = (t == 0) ? xq : (t == 1) ? xk : xv;
        dst = (t == 0) ? oq : (t == 1) ? ok : ov;
    } else {
        int wb = bid - 24576;
        int t = wb >> 10;
        lb = (size_t)(wb & 1023);
        src = (t == 0) ? wq : (t == 1) ? wk : (t == 2) ? wv : wo;
        dst = (t == 0) ? owq : (t == 1) ? owk : (t == 2) ? owv : owo;
    }
    size_t i = (lb * 256 + threadIdx.x) * 4;
    float4 v = *(const float4*)(src + i);
    size_t base = (i >> 1) & ~(size_t)31;
    int p0 = (int)(i & 63) >> 1;
    dst[base + sigma(p0)    ] = packh2(v.x, v.y);
    dst[base + sigma(p0 + 1)] = packh2(v.z, v.w);
}

// ---------------------------------------------------------------------------
// fp16 tensor-core GEMM v1 (keeper): warp tile 64x32, 256 thr (8 warps, 2x4),
// 3-stage cp.async pipeline, 2 CTAs/SM = 4 warps/SMSP.
// ---------------------------------------------------------------------------
#define GSTR 36
#define GSTG (128 * GSTR)
template<int PERM>
__device__ __forceinline__ void gemm_body(
    const unsigned* __restrict__ A, const unsigned* __restrict__ W,
    const float* __restrict__ bias, void* __restrict__ Cv,
    int M, int N, int K, float oscale)
{
    extern __shared__ unsigned smu[];

    const int tid  = threadIdx.x;
    const int lane = tid & 31, warp = tid >> 5;
    const int wy = warp >> 2, wx = warp & 3;
    const int m0 = wy * 64, n0 = wx * 32;
    const int r = lane >> 2, q = lane & 3;
    const int bm = blockIdx.y * 128, bn = blockIdx.x * 128;
    const int K2 = K >> 1;

    float acc[4][4][4];
    #pragma unroll
    for (int mt = 0; mt < 4; mt++)
        #pragma unroll
        for (int nt = 0; nt < 4; nt++)
            #pragma unroll
            for (int i = 0; i < 4; i++) acc[mt][nt][i] = 0.0f;

    const int NK = K / 64;

    auto load_stage = [&](int kt, int buf) {
        const unsigned* Ag = A + (size_t)bm * K2 + kt * 32;
        const unsigned* Wg = W + (size_t)bn * K2 + kt * 32;
        unsigned* as = smu + buf * 2 * GSTG;
        unsigned* ws = as + GSTG;
        #pragma unroll
        for (int i = 0; i < 4; i++) {
            int idx = tid + i * 256;
            int row = idx >> 3, u = idx & 7;
            cp16(&as[row * GSTR + u * 4], Ag + (size_t)row * K2 + u * 4);
            cp16(&ws[row * GSTR + u * 4], Wg + (size_t)row * K2 + u * 4);
        }
        CP_COMMIT;
    };

    load_stage(0, 0);
    if (NK > 1) load_stage(1, 1);

    for (int kt = 0; kt < NK; kt++) {
        if (kt + 1 < NK) { CP_WAIT1; } else { CP_WAIT0; }
        __syncthreads();
        if (kt + 2 < NK) load_stage(kt + 2, (kt + 2) % 3);

        const unsigned* as = smu + (kt % 3) * 2 * GSTG;
        const unsigned* ws = as + GSTG;

        unsigned bch[4][8];
        #pragma unroll
        for (int nt = 0; nt < 4; nt++) {
            const uint4* bp = (const uint4*)(ws + (n0 + nt * 8 + r) * GSTR + q * 8);
            uint4 u0 = bp[0], u1 = bp[1];
            bch[nt][0]=u0.x; bch[nt][1]=u0.y; bch[nt][2]=u0.z; bch[nt][3]=u0.w;
            bch[nt][4]=u1.x; bch[nt][5]=u1.y; bch[nt][6]=u1.z; bch[nt][7]=u1.w;
        }

        #pragma unroll
        for (int mt = 0; mt < 4; mt++) {
            const uint4* ap0 = (const uint4*)(as + (m0 + mt * 16 + r    ) * GSTR + q * 8);
            const uint4* ap1 = (const uint4*)(as + (m0 + mt * 16 + r + 8) * GSTR + q * 8);
            uint4 a00 = ap0[0], a01 = ap0[1], a10 = ap1[0], a11 = ap1[1];
            unsigned ar0[8] = {a00.x,a00.y,a00.z,a00.w, a01.x,a01.y,a01.z,a01.w};
            unsigned ar1[8] = {a10.x,a10.y,a10.z,a10.w, a11.x,a11.y,a11.z,a11.w};
            #pragma unroll
            for (int nt = 0; nt < 4; nt++) {
                #pragma unroll
                for (int ks = 0; ks < 4; ks++) {
                    unsigned af[4] = { ar0[2*ks], ar1[2*ks], ar0[2*ks+1], ar1[2*ks+1] };
                    unsigned bf[2] = { bch[nt][2*ks], bch[nt][2*ks+1] };
                    mma_f16(acc[mt][nt], af, bf, acc[mt][nt]);
                }
            }
        }
    }

    if (PERM == 3) {
        __syncthreads();
        __half* Vts = (__half*)smu;
        #pragma unroll
        for (int mt = 0; mt < 4; mt++) {
            #pragma unroll
            for (int nt = 0; nt < 4; nt++) {
                int col = bn + n0 + nt * 8 + 2 * q;
                float2 bv = *(const float2*)&bias[col];
                int tok = m0 + mt * 16 + r;
                int dc  = n0 + nt * 8 + 2 * q;
                Vts[ dc      * 136 + tok    ] = __float2half_rn(acc[mt][nt][0] + bv.x);
                Vts[(dc + 1) * 136 + tok    ] = __float2half_rn(acc[mt][nt][1] + bv.y);
                Vts[ dc      * 136 + tok + 8] = __float2half_rn(acc[mt][nt][2] + bv.x);
                Vts[(dc + 1) * 136 + tok + 8] = __float2half_rn(acc[mt][nt][3] + bv.y);
            }
        }
        __syncthreads();
        const unsigned* Vtu = (const unsigned*)Vts;
        unsigned* Co = (unsigned*)Cv;
        for (int f = tid; f < 128 * 64; f += 256) {
            int d = f >> 6, slot = f & 63;
            int tile = slot >> 5, g = slot & 31;
            int p = ((g >> 1) & 3) * 8 + (g & 1) * 4 + (g >> 3);  // sigma^-1
            unsigned val = Vtu[d * 68 + tile * 32 + p];
            int gc = bn + d;
            int head = gc >> 6, dl = gc & 63;
            int bb = (bm + tile * 64) >> 11;
            int tib = ((bm & 2047) >> 6) + tile;
            Co[((size_t)(bb * HH + head) * 64 + dl) * 1024 + (size_t)tib * 32 + g] = val;
        }
        return;
    }

    #pragma unroll
    for (int mt = 0; mt < 4; mt++) {
        #pragma unroll
        for (int nt = 0; nt < 4; nt++) {
            int col = bn + n0 + nt * 8 + 2 * q;
            float2 bv = *(const float2*)&bias[col];
            int row0 = bm + m0 + mt * 16 + r;
            float v00 = (acc[mt][nt][0] + bv.x) * oscale;
            float v01 = (acc[mt][nt][1] + bv.y) * oscale;
            float v10 = (acc[mt][nt][2] + bv.x) * oscale;
            float v11 = (acc[mt][nt][3] + bv.y) * oscale;
            if (PERM == 0) {
                float* Cf = (float*)Cv;
                *(float2*)&Cf[(size_t)row0     * N + col] = make_float2(v00, v01);
                *(float2*)&Cf[(size_t)(row0+8) * N + col] = make_float2(v10, v11);
            } else {
                unsigned* Cu = (unsigned*)Cv;
                int slot = sigma((col & 63) >> 1);
                size_t base = (size_t)row0 * (N >> 1) + ((col >> 6) << 5) + slot;
                Cu[base]                 = packh2(v00, v01);
                Cu[base + 8 * (N >> 1)]  = packh2(v10, v11);
            }
        }
    }
}

__global__ __launch_bounds__(256, 2) void gemm_qkv(
    const unsigned* __restrict__ xq, const unsigned* __restrict__ xk, const unsigned* __restrict__ xv,
    const unsigned* __restrict__ Wq, const unsigned* __restrict__ Wk, const unsigned* __restrict__ Wv,
    const float* __restrict__ bq, const float* __restrict__ bk, const float* __restrict__ bv,
    __half* __restrict__ Qd, __half* __restrict__ Kd, __half* __restrict__ Vd)
{
    const int z = blockIdx.z;
    if      (z == 0) gemm_body<1>(xq, Wq, bq, (void*)Qd, MROWS, DD, DD, 0.18033688f);
    else if (z == 1) gemm_body<1>(xk, Wk, bk, (void*)Kd, MROWS, DD, DD, 1.0f);
    else             gemm_body<3>(xv, Wv, bv, (void*)Vd, MROWS, DD, DD, 1.0f);
}

__global__ __launch_bounds__(256, 2) void gemm_out(
    const unsigned* __restrict__ A, const unsigned* __restrict__ W,
    const float* __restrict__ bias, float* __restrict__ C)
{
    gemm_body<0>(A, W, bias, (void*)C, MROWS, DD, DD, 1.0f);
}

// ---------------------------------------------------------------------------
// fp16 flash attention v14: v13 structure (32 q-rows/warp, 128-thr CTAs,
// 3 CTAs/SM, two key-pair passes) with QK in f16-ACCUMULATOR mma: the packed
// C fragment {(r,2q),(r,2q+1)} feeds ex2h2 directly — all 32 packh2 per
// warp/tile eliminated, and f16-dst HMMA may run at double rate.
// ---------------------------------------------------------------------------
#define KVSTR 36
#define QT   128
#define KVSTG (2 * 64 * KVSTR)
__global__ __launch_bounds__(128, 3) void attn_tc(
    const unsigned* __restrict__ Q, const unsigned* __restrict__ K,
    const unsigned* __restrict__ V, unsigned* __restrict__ Out)
{
    extern __shared__ unsigned smu[];
    unsigned* Qs = smu + 3 * KVSTG;   // [128][36] u32

    const int tid  = threadIdx.x;
    const int lane = tid & 31, warp = tid >> 5;   // 4 warps
    const int m0 = warp * 32;                     // 32 q-rows per warp
    const int r = lane >> 2, q = lane & 3;
    const int qt = blockIdx.x, bh = blockIdx.y;
    const int b = bh >> 4, h = bh & 15;

    const unsigned* Qg = Q + ((size_t)(b * SS + qt * QT)) * 512 + h * 32;
    const unsigned* Kg = K + ((size_t)(b * SS)) * 512 + h * 32;
    const unsigned* Vg = V + ((size_t)(b * HH + h) * 64) * 1024;

    #pragma unroll
    for (int i = 0; i < 8; i++) {
        int idx = tid + i * 128;
        int row = idx >> 3, u = idx & 7;
        cp16(&Qs[row * KVSTR + u * 4], Qg + (size_t)row * 512 + u * 4);
    }
    CP_COMMIT;

    auto load_stage = [&](int kt, int buf) {
        unsigned* ks_ = smu + buf * KVSTG;
        unsigned* vs_ = ks_ + 64 * KVSTR;
        #pragma unroll
        for (int i = 0; i < 4; i++) {
            int idx = tid + i * 128;
            int row = idx >> 3, u = idx & 7;
            cp16(&ks_[row * KVSTR + u * 4], Kg + (size_t)(kt * 64 + row) * 512 + u * 4);
            cp16(&vs_[row * KVSTR + u * 4], Vg + (size_t)row * 1024 + kt * 32 + u * 4);
        }
        CP_COMMIT;
    };
    load_stage(0, 0);
    load_stage(1, 1);

    CP_WAIT2;          // Q done
    __syncthreads();

    unsigned qa[2][4][4];
    #pragma unroll
    for (int mt = 0; mt < 2; mt++) {
        const uint4* qp0 = (const uint4*)(Qs + (m0 + mt * 16 + r    ) * KVSTR + q * 8);
        const uint4* qp1 = (const uint4*)(Qs + (m0 + mt * 16 + r + 8) * KVSTR + q * 8);
        uint4 a00 = qp0[0], a01 = qp0[1], a10 = qp1[0], a11 = qp1[1];
        unsigned ar0[8] = {a00.x,a00.y,a00.z,a00.w, a01.x,a01.y,a01.z,a01.w};
        unsigned ar1[8] = {a10.x,a10.y,a10.z,a10.w, a11.x,a11.y,a11.z,a11.w};
        #pragma unroll
        for (int ks = 0; ks < 4; ks++) {
            qa[mt][ks][0] = ar0[2*ks];
            qa[mt][ks][1] = ar1[2*ks];
            qa[mt][ks][2] = ar0[2*ks+1];
            qa[mt][ks][3] = ar1[2*ks+1];
        }
    }

    float O[2][8][4];
    #pragma unroll
    for (int mt = 0; mt < 2; mt++)
        #pragma unroll
        for (int nt = 0; nt < 8; nt++)
            #pragma unroll
            for (int i = 0; i < 4; i++) O[mt][nt][i] = 0.0f;
    float Ol[2][4] = {};
    const unsigned onesb[2] = { 0x3C003C00u, 0x3C003C00u };

    const int NT = SS / 64;
    for (int kt = 0; kt < NT; kt++) {
        if (kt + 1 < NT) { CP_WAIT1; } else { CP_WAIT0; }
        __syncthreads();
        if (kt + 2 < NT) load_stage(kt + 2, (kt + 2) % 3);

        const unsigned* Ks = smu + (kt % 3) * KVSTG;
        const unsigned* Vs = Ks + 64 * KVSTR;

        #pragma unroll
        for (int tp = 0; tp < 2; tp++) {
            unsigned pa[2][2][4];
            #pragma unroll
            for (int ntl = 0; ntl < 4; ntl++) {
                int nt = tp * 4 + ntl;
                const uint4* kp = (const uint4*)(Ks + (nt * 8 + r) * KVSTR + q * 8);
                uint4 u0 = kp[0], u1 = kp[1];
                unsigned ch[8] = {u0.x,u0.y,u0.z,u0.w, u1.x,u1.y,u1.z,u1.w};
                unsigned sh0[2] = {0u, 0u}, sh1[2] = {0u, 0u};   // f16x2 accum
                #pragma unroll
                for (int ks = 0; ks < 4; ks++) {
                    unsigned bf[2] = { ch[2*ks], ch[2*ks+1] };
                    mma_f16c16(sh0, qa[0][ks], bf, sh0);
                    mma_f16c16(sh1, qa[1][ks], bf, sh1);
                }
                int tl = ntl >> 1, j = ntl & 1;
                pa[0][tl][2*j    ] = ex2h2(sh0[0]);   // rows r   : cols 2q,2q+1
                pa[0][tl][2*j + 1] = ex2h2(sh0[1]);   // rows r+8
                pa[1][tl][2*j    ] = ex2h2(sh1[0]);
                pa[1][tl][2*j + 1] = ex2h2(sh1[1]);
            }

            #pragma unroll
            for (int tl = 0; tl < 2; tl++) {
                mma_f16(Ol[0], pa[0][tl], onesb, Ol[0]);
                mma_f16(Ol[1], pa[1][tl], onesb, Ol[1]);
            }

            #pragma unroll
            for (int nt = 0; nt < 8; nt++) {
                uint4 v = *(const uint4*)(Vs + (nt * 8 + r) * KVSTR + q * 8 + tp * 4);
                unsigned bf0[2] = { v.x, v.y };
                unsigned bf1[2] = { v.z, v.w };
                mma_f16(O[0][nt], pa[0][0], bf0, O[0][nt]);
                mma_f16(O[0][nt], pa[0][1], bf1, O[0][nt]);
                mma_f16(O[1][nt], pa[1][0], bf0, O[1][nt]);
                mma_f16(O[1][nt], pa[1][1], bf1, O[1][nt]);
            }
        }
    }

    unsigned* Og = Out + ((size_t)(b * SS + qt * QT)) * 512 + h * 32;
    #pragma unroll
    for (int mt = 0; mt < 2; mt++) {
        float inv0 = 1.0f / Ol[mt][0], inv1 = 1.0f / Ol[mt][2];
        #pragma unroll
        for (int nt = 0; nt < 8; nt++) {
            int c0 = nt * 8 + 2 * q;
            int slot = sigma(c0 >> 1);
            size_t ra = (size_t)(m0 + mt * 16 + r    ) * 512;
            size_t rb = (size_t)(m0 + mt * 16 + r + 8) * 512;
            Og[ra + slot] = packh2(O[mt][nt][0] * inv0, O[mt][nt][1] * inv0);
            Og[rb + slot] = packh2(O[mt][nt][2] * inv1, O[mt][nt][3] * inv1);
        }
    }
}

// ---------------------------------------------------------------------------
extern "C" void kernel_launch(void* const* d_in, const int* in_sizes, int n_in,
                              void* d_out, int out_size)
{
    const float* query = (const float*)d_in[0];
    const float* key_  = (const float*)d_in[1];
    const float* value = (const float*)d_in[2];
    const float* Wq    = (const float*)d_in[3];
    const float* bq    = (const float*)d_in[4];
    const float* Wk    = (const float*)d_in[5];
    const float* bk    = (const float*)d_in[6];
    const float* Wv    = (const float*)d_in[7];
    const float* bv    = (const float*)d_in[8];
    const float* Wo    = (const float*)d_in[9];
    const float* bo    = (const float*)d_in[10];
    float* out = (float*)d_out;

    __half *Qd, *Kd, *Vd, *Cd, *Xq, *Xk, *Xv, *Wqh, *Wkh, *Wvh, *Woh;
    cudaGetSymbolAddress((void**)&Qd,  g_Qh);
    cudaGetSymbolAddress((void**)&Kd,  g_Kh);
    cudaGetSymbolAddress((void**)&Vd,  g_Vh);
    cudaGetSymbolAddress((void**)&Cd,  g_Ch);
    cudaGetSymbolAddress((void**)&Xq,  g_Xq);
    cudaGetSymbolAddress((void**)&Xk,  g_Xk);
    cudaGetSymbolAddress((void**)&Xv,  g_Xv);
    cudaGetSymbolAddress((void**)&Wqh, g_Wqh);
    cudaGetSymbolAddress((void**)&Wkh, g_Wkh);
    cudaGetSymbolAddress((void**)&Wvh, g_Wvh);
    cudaGetSymbolAddress((void**)&Woh, g_Woh);

    const int gemm_smem = 3 * 2 * GSTG * 4;                     // 110592
    const int attn_smem = (3 * KVSTG + QT * KVSTR) * 4;         // 73728
    cudaFuncSetAttribute(gemm_qkv, cudaFuncAttributeMaxDynamicSharedMemorySize, gemm_smem);
    cudaFuncSetAttribute(gemm_out, cudaFuncAttributeMaxDynamicSharedMemorySize, gemm_smem);
    cudaFuncSetAttribute(attn_tc,  cudaFuncAttributeMaxDynamicSharedMemorySize, attn_smem);

    cvt_all<<<28672, 256>>>(query, key_, value, Wq, Wk, Wv, Wo,
                            (unsigned*)Xq, (unsigned*)Xk, (unsigned*)Xv,
                            (unsigned*)Wqh, (unsigned*)Wkh,
                            (unsigned*)Wvh, (unsigned*)Woh);

    dim3 qkvgrid(DD / 128, MROWS / 128, 3);   // (8, 64, 3)
    gemm_qkv<<<qkvgrid, 256, gemm_smem>>>((const unsigned*)Xq, (const unsigned*)Xk,
                                          (const unsigned*)Xv, (const unsigned*)Wqh,
                                          (const unsigned*)Wkh, (const unsigned*)Wvh,
                                          bq, bk, bv, Qd, Kd, Vd);

    attn_tc<<<dim3(SS / QT, BB * HH), 128, attn_smem>>>(
        (const unsigned*)Qd, (const unsigned*)Kd, (const unsigned*)Vd, (unsigned*)Cd);

    dim3 ogrid(DD / 128, MROWS / 128);        // (8, 64)
    gemm_out<<<ogrid, 256, gemm_smem>>>((const unsigned*)Cd, (const unsigned*)Woh, bo, out);
}